// round 16
// baseline (speedup 1.0000x reference)
#include <cuda_runtime.h>

#define Nn      1000
#define NP      1024
#define Bb      8
#define GRID    125
#define NTHREAD 512

// Scratch (static __device__ — no allocation). Padded to NP.
__device__ float4 g_EA[NP];
__device__ float4 g_EB[NP];       // pad rows = (0,0,0,1) -> d contribution 1, w = 0
__device__ float4 g_xt[2 * NP];   // xt[i] = x[0..7][i] transposed; pad rows = 0
__device__ unsigned long long g_bar = 0ULL;   // monotonic ticket counter (never reset)

// ---- packed f32x2 helper (Blackwell) ----
__device__ __forceinline__ void ffma2(float2& d, const float2 a, const float2 b) {
    asm("fma.rn.f32x2 %0, %1, %2, %0;"
        : "+l"(reinterpret_cast<unsigned long long&>(d))
        : "l"(reinterpret_cast<const unsigned long long&>(a)),
          "l"(reinterpret_cast<const unsigned long long&>(b)));
}

// ---------------------------------------------------------------------------
// Single persistent kernel: 125 blocks x 512 threads (R15 structure).
// Phase 1 (latency-overlapped): tid<8 loads its 8 rows; ALL threads stream x
// for the global sum X; warp 1 concurrently loads all weights (one MLP'd
// miss) and computes X-FREE coefficient parts. ONE syncthreads; tid<8 folds
// X in and writes EA/EB. Grid ticket barrier with fences hoisted into the
// single barrier thread (CG grid.sync pattern — avoids 1024 per-block
// MEMBAR.GPU/CCTL.IVALL). Phase 2: R9 verbatim.
// ---------------------------------------------------------------------------
__global__ void __launch_bounds__(NTHREAD, 1) k_all(
    const float* __restrict__ x,
    const float* __restrict__ W1,   const float* __restrict__ b1,
    const float* __restrict__ W2,   const float* __restrict__ b2,
    const float* __restrict__ Wf1e, const float* __restrict__ bf1e,
    const float* __restrict__ Wf2e, const float* __restrict__ bf2e,
    const float* __restrict__ Wfk,  const float* __restrict__ bfk,
    const float* __restrict__ Wf1v, const float* __restrict__ bf1v,
    const float* __restrict__ Wf2v, const float* __restrict__ bf2v,
    float* __restrict__ out)
{
    __shared__ float s_w[16];
    __shared__ float s_cf[18];       // aA[3], cAx[3], cA0[3], aB[3], cBx[3], cB0[3]
    __shared__ float s_cc[24];       // c0/c1/c2 [k][m] (18) + Wf2v (3) + bf2v (1)
    __shared__ float s_v[16][32];    // per-warp reduced slots

    const int tid = threadIdx.x;
    const int bid = blockIdx.x;

    // ===================== Phase 1 (overlapped) =============================
    // (A) my 8 rows: transpose + row-sum (issue these strided loads first)
    const int myrow = bid * 8 + tid;          // valid for tid < 8
    float sxi = 0.f;
    if (tid < 8) {
        float vr[8];
        #pragma unroll
        for (int b = 0; b < 8; b++) {
            vr[b] = x[b * Nn + myrow];
            sxi += vr[b];
        }
        g_xt[2 * myrow]     = make_float4(vr[0], vr[1], vr[2], vr[3]);
        g_xt[2 * myrow + 1] = make_float4(vr[4], vr[5], vr[6], vr[7]);
    } else if (bid == GRID - 1 && tid >= 8 && tid < 32) {
        // pad rows 1000..1023 (24 rows)
        const int p = Nn + (tid - 8);
        g_xt[2 * p]     = make_float4(0.f, 0.f, 0.f, 0.f);
        g_xt[2 * p + 1] = make_float4(0.f, 0.f, 0.f, 0.f);
        g_EA[p] = make_float4(0.f, 0.f, 0.f, 0.f);
        g_EB[p] = make_float4(0.f, 0.f, 0.f, 1.f);   // d += 1, w = 0
    }

    // (B) warp 1: weights -> X-free coefficient parts + combine constants.
    if (tid >= 32 && tid < 64) {
        // Wf1e shape: (2*EMB, F1E) = (8, 2) -> 16 floats
        float w1[4], bb1[4], wf1e[16], bv1e[2], wf1v[6], bv1v[3], wf2e[18], bv2e[3];
        #pragma unroll
        for (int e = 0; e < 4; e++) { w1[e] = W1[e]; bb1[e] = b1[e]; }
        #pragma unroll
        for (int q = 0; q < 16; q++) wf1e[q] = Wf1e[q];
        bv1e[0] = bf1e[0]; bv1e[1] = bf1e[1];
        #pragma unroll
        for (int q = 0; q < 6; q++) wf1v[q] = Wf1v[q];
        bv1v[0] = bf1v[0]; bv1v[1] = bf1v[1]; bv1v[2] = bf1v[2];
        #pragma unroll
        for (int q = 0; q < 18; q++) wf2e[q] = Wf2e[q];
        bv2e[0] = bf2e[0]; bv2e[1] = bf2e[1]; bv2e[2] = bf2e[2];

        float alpha[2], beta[2], gamma[2];
        #pragma unroll
        for (int f = 0; f < 2; f++) {
            float sa = 0.f, sb = 0.f, sg = 0.f;
            #pragma unroll
            for (int e = 0; e < 4; e++) {
                float we = wf1e[(2 * e) * 2 + f];
                float wo = wf1e[(2 * e + 1) * 2 + f];
                sa += w1[e] * we;
                sb += w1[e] * wo;
                sg += bb1[e] * (we + wo);
            }
            alpha[f] = (float)Nn * sa;
            beta[f]  = sb;
            gamma[f] = (float)Nn * (sg + bv1e[f]);
        }
        float ap[3], bq[3], gg[3];
        #pragma unroll
        for (int vv = 0; vv < 3; vv++) {
            float a = 0.f, bqv = 0.f, ggv = 0.f;
            #pragma unroll
            for (int f = 0; f < 2; f++) {
                float w = wf1v[f * 3 + vv];
                a   += alpha[f] * w;
                bqv += beta[f]  * w;
                ggv += gamma[f] * w;
            }
            ap[vv] = a;
            bq[vv] = bqv;
            gg[vv] = ggv + bv1v[vv];
        }
        if (tid == 32) {
            #pragma unroll
            for (int k = 0; k < 3; k++) {
                float sA = 0.f, sAx = 0.f, sA0 = 0.f;
                float sB = 0.f, sBx = 0.f, sB0 = 0.f;
                #pragma unroll
                for (int vv = 0; vv < 3; vv++) {
                    float we = wf2e[(2 * vv) * 3 + k];
                    float wo = wf2e[(2 * vv + 1) * 3 + k];
                    sA  += ap[vv] * we;  sAx += bq[vv] * we;  sA0 += gg[vv] * we;
                    sB  += ap[vv] * wo;  sBx += bq[vv] * wo;  sB0 += gg[vv] * wo;
                }
                s_cf[k]      = sA;                          // aA
                s_cf[3 + k]  = sAx;                         // cAx
                s_cf[6 + k]  = (float)Bb * sA0 + bv2e[k];   // cA0 (+bias)
                s_cf[9 + k]  = sB;                          // aB
                s_cf[12 + k] = sBx;                         // cBx
                s_cf[15 + k] = (float)Bb * sB0;             // cB0
            }
            // combine constants (X-free), block-local
            #pragma unroll
            for (int k = 0; k < 3; k++)
                #pragma unroll
                for (int m = 0; m < 2; m++) {
                    float u1 = 0.f, v1 = 0.f, u2 = 0.f, v2 = 0.f;
                    #pragma unroll
                    for (int e = 0; e < 4; e++) {
                        float we = Wfk[k * 16 + (2 * e) * 2 + m];
                        float wo = Wfk[k * 16 + (2 * e + 1) * 2 + m];
                        u1 += W2[e] * we;  v1 += b2[e] * we;
                        u2 += W2[e] * wo;  v2 += b2[e] * wo;
                    }
                    int km = k * 2 + m;
                    s_cc[km * 3 + 0] = v1 + v2 + bfk[km];
                    s_cc[km * 3 + 1] = u1;
                    s_cc[km * 3 + 2] = u2;
                }
            s_cc[18] = Wf2v[0]; s_cc[19] = Wf2v[1];
            s_cc[20] = Wf2v[2]; s_cc[21] = bf2v[0];
        }
    }

    // (C) all threads: global-X partials (contiguous x as 2000 float4)
    {
        const float4* x4 = (const float4*)x;
        float xs = 0.f;
        #pragma unroll 1
        for (int t = tid; t < 2000; t += NTHREAD) {
            float4 a = x4[t];
            xs += (a.x + a.y) + (a.z + a.w);
        }
        #pragma unroll
        for (int off = 16; off > 0; off >>= 1)
            xs += __shfl_xor_sync(0xffffffffu, xs, off);
        if ((tid & 31) == 0) s_w[tid >> 5] = xs;
    }
    __syncthreads();    // single block-level sync: s_w, s_cf, s_cc all ready

    // (D) tid<8: fold X in, compute EA/EB (per-side max-subtracted; exact)
    if (tid < 8) {
        float X = 0.f;
        #pragma unroll
        for (int w = 0; w < 16; w++) X += s_w[w];    // fixed order
        float A0 = fmaf(s_cf[0], sxi, fmaf(s_cf[3], X, s_cf[6]));
        float A1 = fmaf(s_cf[1], sxi, fmaf(s_cf[4], X, s_cf[7]));
        float A2 = fmaf(s_cf[2], sxi, fmaf(s_cf[5], X, s_cf[8]));
        float mA = fmaxf(A0, fmaxf(A1, A2));
        g_EA[myrow] = make_float4(__expf(A0 - mA), __expf(A1 - mA), __expf(A2 - mA), 0.f);
        float B0 = fmaf(s_cf[9],  sxi, fmaf(s_cf[12], X, s_cf[15]));
        float B1 = fmaf(s_cf[10], sxi, fmaf(s_cf[13], X, s_cf[16]));
        float B2 = fmaf(s_cf[11], sxi, fmaf(s_cf[14], X, s_cf[17]));
        float mB = fmaxf(B0, fmaxf(B1, B2));
        g_EB[myrow] = make_float4(__expf(B0 - mB), __expf(B1 - mB), __expf(B2 - mB), 0.f);
    }

    // ===== grid-wide ticket barrier: fences hoisted into ONE thread =========
    // (cooperative-groups grid.sync pattern; cumulative fences + syncthreads
    //  provide release/acquire for the whole block at 2 fences/block total)
    __syncthreads();
    if (tid == 0) {
        __threadfence();                    // release (cumulative)
        unsigned long long ticket = atomicAdd(&g_bar, 1ULL);
        unsigned long long target = ticket - (ticket % GRID) + GRID;
        while (*(volatile unsigned long long*)&g_bar < target) { }
        __threadfence();                    // acquire (one L1D invalidate/SM)
    }
    __syncthreads();

    // ===================== Phase 2: R9 verbatim =============================
    const int lane = tid & 31;
    const int warp = tid >> 5;              // 0..15
    const int r    = warp >> 1;             // 0..7
    const int h    = warp & 1;              // half: j in [h*512, h*512+512)
    const int i    = bid * 8 + r;           // 0..999
    const float4 ea = g_EA[i];
    const float eav[3] = {ea.x, ea.y, ea.z};

    // folded coefficients q[m][k] = c2[k,m] * ea_k  (from smem)
    float q0[3], q1[3];
    #pragma unroll
    for (int k = 0; k < 3; k++) {
        q0[k] = s_cc[(k * 2 + 0) * 3 + 2] * eav[k];
        q1[k] = s_cc[(k * 2 + 1) * 3 + 2] * eav[k];
    }

    float t0 = 0.f, t1 = 0.f, t2 = 0.f;
    float2 a0[4], a1[4];
    #pragma unroll
    for (int bp = 0; bp < 4; bp++) {
        a0[bp] = make_float2(0.f, 0.f);
        a1[bp] = make_float2(0.f, 0.f);
    }

    #pragma unroll 1
    for (int u = 0; u < 4; u++) {
        float4 eb[4], xa[4], xb[4];
        #pragma unroll
        for (int t = 0; t < 4; t++) {
            const int j = h * 512 + (u * 4 + t) * 32 + lane;
            eb[t] = g_EB[j];
            xa[t] = g_xt[2 * j];
            xb[t] = g_xt[2 * j + 1];
        }
        float d[4];
        #pragma unroll
        for (int t = 0; t < 4; t++)
            d[t] = fmaf(ea.x, eb[t].x, fmaf(ea.y, eb[t].y, fmaf(ea.z, eb[t].z, eb[t].w)));
        // Montgomery batch inversion: 1 MUFU per 4 pairs; d in (1,4] -> safe
        float p1 = d[0] * d[1];
        float p2 = p1 * d[2];
        float p3 = p2 * d[3];
        float rr = __fdividef(1.f, p3);
        float inv[4];
        inv[3]   = rr * p2;
        float r2 = rr * d[3];
        inv[2]   = r2 * p1;
        float r1 = r2 * d[2];
        inv[1]   = r1 * d[0];
        inv[0]   = r1 * d[1];

        #pragma unroll
        for (int t = 0; t < 4; t++) {
            float w0 = eb[t].x * inv[t];
            float w1 = eb[t].y * inv[t];
            float w2 = eb[t].z * inv[t];
            t0 += w0; t1 += w1; t2 += w2;
            float s0 = fmaf(q0[0], w0, fmaf(q0[1], w1, q0[2] * w2));
            float s1 = fmaf(q1[0], w0, fmaf(q1[1], w1, q1[2] * w2));
            float2 xp[4] = { make_float2(xa[t].x, xa[t].y), make_float2(xa[t].z, xa[t].w),
                             make_float2(xb[t].x, xb[t].y), make_float2(xb[t].z, xb[t].w) };
            float2 sp0 = make_float2(s0, s0);
            float2 sp1 = make_float2(s1, s1);
            #pragma unroll
            for (int bp = 0; bp < 4; bp++) {
                ffma2(a0[bp], sp0, xp[bp]);
                ffma2(a1[bp], sp1, xp[bp]);
            }
        }
    }

    // 19 values -> 32 slots; distributed exchange reduce within warp
    float vv[32];
    vv[0] = t0; vv[1] = t1; vv[2] = t2;
    #pragma unroll
    for (int bp = 0; bp < 4; bp++) {
        vv[3 + 2 * bp]      = a0[bp].x;  vv[3 + 2 * bp + 1]  = a0[bp].y;
        vv[11 + 2 * bp]     = a1[bp].x;  vv[11 + 2 * bp + 1] = a1[bp].y;
    }
    #pragma unroll
    for (int s = 19; s < 32; s++) vv[s] = 0.f;

    #pragma unroll
    for (int lev = 0; lev < 5; lev++) {
        const int dd = 1 << lev;
        const int half = 16 >> lev;
        const bool up = (lane & dd) != 0;
        #pragma unroll
        for (int s = 0; s < half; s++) {
            float keep = up ? vv[s + half] : vv[s];
            float send = up ? vv[s] : vv[s + half];
            float recv = __shfl_xor_sync(0xffffffffu, send, dd);
            vv[s] = keep + recv;
        }
    }
    const int br = ((lane & 1) << 4) | ((lane & 2) << 2) | (lane & 4)
                 | ((lane & 8) >> 2) | ((lane & 16) >> 4);
    s_v[warp][br] = vv[0];
    __syncthreads();

    // even warp of each pair finishes the row: lanes 0..7 -> 8 batch outputs
    if (h == 0 && lane < 8) {
        const int b = lane;
        const int w0i = 2 * r, w1i = 2 * r + 1;
        float xbi = ((const float*)&g_xt[2 * i])[b];
        float T0 = s_v[w0i][0] + s_v[w1i][0];
        float T1 = s_v[w0i][1] + s_v[w1i][1];
        float T2 = s_v[w0i][2] + s_v[w1i][2];
        float V0 = s_v[w0i][3 + b]  + s_v[w1i][3 + b];
        float V1 = s_v[w0i][11 + b] + s_v[w1i][11 + b];
        float eaT[3] = {eav[0] * T0, eav[1] * T1, eav[2] * T2};
        float ve0 = V0, ve1 = V1;
        #pragma unroll
        for (int k = 0; k < 3; k++) {
            ve0 += fmaf(xbi, s_cc[(k * 2 + 0) * 3 + 1], s_cc[(k * 2 + 0) * 3 + 0]) * eaT[k];
            ve1 += fmaf(xbi, s_cc[(k * 2 + 1) * 3 + 1], s_cc[(k * 2 + 1) * 3 + 0]) * eaT[k];
        }
        out[b * Nn + i] = xbi * (1.f + s_cc[20]) + s_cc[21]
                        + ve0 * s_cc[18] + ve1 * s_cc[19];
    }
}

extern "C" void kernel_launch(void* const* d_in, const int* in_sizes, int n_in,
                              void* d_out, int out_size)
{
    (void)in_sizes; (void)n_in; (void)out_size;
    k_all<<<GRID, NTHREAD>>>(
        (const float*)d_in[0],
        (const float*)d_in[1],  (const float*)d_in[2],
        (const float*)d_in[3],  (const float*)d_in[4],
        (const float*)d_in[5],  (const float*)d_in[6],
        (const float*)d_in[7],  (const float*)d_in[8],
        (const float*)d_in[9],  (const float*)d_in[10],
        (const float*)d_in[11], (const float*)d_in[12],
        (const float*)d_in[13], (const float*)d_in[14],
        (float*)d_out);
}

// round 17
// speedup vs baseline: 1.0150x; 1.0150x over previous
#include <cuda_runtime.h>

#define Nn      1000
#define NP      1024
#define Bb      8
#define GRID    125
#define NTHREAD 512

// Scratch (static __device__ — no allocation). Padded to NP.
__device__ float4 g_EA[NP];
__device__ float4 g_EB[NP];       // pad rows = (0,0,0,1) -> d contribution 1, w = 0
__device__ float4 g_xt[2 * NP];   // xt[i] = x[0..7][i] transposed; pad rows = 0
__device__ unsigned long long g_bar = 0ULL;   // monotonic ticket counter (never reset)

// ---- packed f32x2 helper (Blackwell) ----
__device__ __forceinline__ void ffma2(float2& d, const float2 a, const float2 b) {
    asm("fma.rn.f32x2 %0, %1, %2, %0;"
        : "+l"(reinterpret_cast<unsigned long long&>(d))
        : "l"(reinterpret_cast<const unsigned long long&>(a)),
          "l"(reinterpret_cast<const unsigned long long&>(b)));
}

// ---------------------------------------------------------------------------
// Single persistent kernel: 125 blocks x 512 threads.
// Phase 1: overlapped (rows + redundant X + warp-1 coefficients), one sync.
// Grid ticket barrier (fences hoisted into barrier thread).
// Phase 2: TWO ROWS PER WARP, j-quarter split. warp = (row-pair p, quarter q).
// Each (eb, xa, xb) load feeds both rows: loads/FMA halved, ILP doubled.
// Montgomery-8 across both rows (1 MUFU / 8 pair-rows). Two interleaved
// 32-slot exchange reductions; q==0 warps write both rows' outputs.
// ---------------------------------------------------------------------------
__global__ void __launch_bounds__(NTHREAD, 1) k_all(
    const float* __restrict__ x,
    const float* __restrict__ W1,   const float* __restrict__ b1,
    const float* __restrict__ W2,   const float* __restrict__ b2,
    const float* __restrict__ Wf1e, const float* __restrict__ bf1e,
    const float* __restrict__ Wf2e, const float* __restrict__ bf2e,
    const float* __restrict__ Wfk,  const float* __restrict__ bfk,
    const float* __restrict__ Wf1v, const float* __restrict__ bf1v,
    const float* __restrict__ Wf2v, const float* __restrict__ bf2v,
    float* __restrict__ out)
{
    __shared__ float s_w[16];
    __shared__ float s_cf[18];       // aA[3], cAx[3], cA0[3], aB[3], cBx[3], cB0[3]
    __shared__ float s_cc[24];       // c0/c1/c2 [k][m] (18) + Wf2v (3) + bf2v (1)
    __shared__ float s_v[16][64];    // per-warp reduced slots (two rows)

    const int tid = threadIdx.x;
    const int bid = blockIdx.x;

    // ===================== Phase 1 (overlapped) =============================
    const int myrow = bid * 8 + tid;          // valid for tid < 8
    float sxi = 0.f;
    if (tid < 8) {
        float vr[8];
        #pragma unroll
        for (int b = 0; b < 8; b++) {
            vr[b] = x[b * Nn + myrow];
            sxi += vr[b];
        }
        g_xt[2 * myrow]     = make_float4(vr[0], vr[1], vr[2], vr[3]);
        g_xt[2 * myrow + 1] = make_float4(vr[4], vr[5], vr[6], vr[7]);
    } else if (bid == GRID - 1 && tid >= 8 && tid < 32) {
        // pad rows 1000..1023 (24 rows)
        const int p = Nn + (tid - 8);
        g_xt[2 * p]     = make_float4(0.f, 0.f, 0.f, 0.f);
        g_xt[2 * p + 1] = make_float4(0.f, 0.f, 0.f, 0.f);
        g_EA[p] = make_float4(0.f, 0.f, 0.f, 0.f);
        g_EB[p] = make_float4(0.f, 0.f, 0.f, 1.f);   // d += 1, w = 0
    }

    // warp 1: weights -> X-free coefficient parts + combine constants
    if (tid >= 32 && tid < 64) {
        // Wf1e shape: (2*EMB, F1E) = (8, 2) -> 16 floats
        float w1[4], bb1[4], wf1e[16], bv1e[2], wf1v[6], bv1v[3], wf2e[18], bv2e[3];
        #pragma unroll
        for (int e = 0; e < 4; e++) { w1[e] = W1[e]; bb1[e] = b1[e]; }
        #pragma unroll
        for (int q = 0; q < 16; q++) wf1e[q] = Wf1e[q];
        bv1e[0] = bf1e[0]; bv1e[1] = bf1e[1];
        #pragma unroll
        for (int q = 0; q < 6; q++) wf1v[q] = Wf1v[q];
        bv1v[0] = bf1v[0]; bv1v[1] = bf1v[1]; bv1v[2] = bf1v[2];
        #pragma unroll
        for (int q = 0; q < 18; q++) wf2e[q] = Wf2e[q];
        bv2e[0] = bf2e[0]; bv2e[1] = bf2e[1]; bv2e[2] = bf2e[2];

        float alpha[2], beta[2], gamma[2];
        #pragma unroll
        for (int f = 0; f < 2; f++) {
            float sa = 0.f, sb = 0.f, sg = 0.f;
            #pragma unroll
            for (int e = 0; e < 4; e++) {
                float we = wf1e[(2 * e) * 2 + f];
                float wo = wf1e[(2 * e + 1) * 2 + f];
                sa += w1[e] * we;
                sb += w1[e] * wo;
                sg += bb1[e] * (we + wo);
            }
            alpha[f] = (float)Nn * sa;
            beta[f]  = sb;
            gamma[f] = (float)Nn * (sg + bv1e[f]);
        }
        float ap[3], bq[3], gg[3];
        #pragma unroll
        for (int vv = 0; vv < 3; vv++) {
            float a = 0.f, bqv = 0.f, ggv = 0.f;
            #pragma unroll
            for (int f = 0; f < 2; f++) {
                float w = wf1v[f * 3 + vv];
                a   += alpha[f] * w;
                bqv += beta[f]  * w;
                ggv += gamma[f] * w;
            }
            ap[vv] = a;
            bq[vv] = bqv;
            gg[vv] = ggv + bv1v[vv];
        }
        if (tid == 32) {
            #pragma unroll
            for (int k = 0; k < 3; k++) {
                float sA = 0.f, sAx = 0.f, sA0 = 0.f;
                float sB = 0.f, sBx = 0.f, sB0 = 0.f;
                #pragma unroll
                for (int vv = 0; vv < 3; vv++) {
                    float we = wf2e[(2 * vv) * 3 + k];
                    float wo = wf2e[(2 * vv + 1) * 3 + k];
                    sA  += ap[vv] * we;  sAx += bq[vv] * we;  sA0 += gg[vv] * we;
                    sB  += ap[vv] * wo;  sBx += bq[vv] * wo;  sB0 += gg[vv] * wo;
                }
                s_cf[k]      = sA;                          // aA
                s_cf[3 + k]  = sAx;                         // cAx
                s_cf[6 + k]  = (float)Bb * sA0 + bv2e[k];   // cA0 (+bias)
                s_cf[9 + k]  = sB;                          // aB
                s_cf[12 + k] = sBx;                         // cBx
                s_cf[15 + k] = (float)Bb * sB0;             // cB0
            }
            #pragma unroll
            for (int k = 0; k < 3; k++)
                #pragma unroll
                for (int m = 0; m < 2; m++) {
                    float u1 = 0.f, v1 = 0.f, u2 = 0.f, v2 = 0.f;
                    #pragma unroll
                    for (int e = 0; e < 4; e++) {
                        float we = Wfk[k * 16 + (2 * e) * 2 + m];
                        float wo = Wfk[k * 16 + (2 * e + 1) * 2 + m];
                        u1 += W2[e] * we;  v1 += b2[e] * we;
                        u2 += W2[e] * wo;  v2 += b2[e] * wo;
                    }
                    int km = k * 2 + m;
                    s_cc[km * 3 + 0] = v1 + v2 + bfk[km];
                    s_cc[km * 3 + 1] = u1;
                    s_cc[km * 3 + 2] = u2;
                }
            s_cc[18] = Wf2v[0]; s_cc[19] = Wf2v[1];
            s_cc[20] = Wf2v[2]; s_cc[21] = bf2v[0];
        }
    }

    // all threads: global-X partials (contiguous x as 2000 float4)
    {
        const float4* x4 = (const float4*)x;
        float xs = 0.f;
        #pragma unroll 1
        for (int t = tid; t < 2000; t += NTHREAD) {
            float4 a = x4[t];
            xs += (a.x + a.y) + (a.z + a.w);
        }
        #pragma unroll
        for (int off = 16; off > 0; off >>= 1)
            xs += __shfl_xor_sync(0xffffffffu, xs, off);
        if ((tid & 31) == 0) s_w[tid >> 5] = xs;
    }
    __syncthreads();    // single block-level sync: s_w, s_cf, s_cc all ready

    // tid<8: fold X in, compute EA/EB (per-side max-subtracted; exact)
    if (tid < 8) {
        float X = 0.f;
        #pragma unroll
        for (int w = 0; w < 16; w++) X += s_w[w];    // fixed order
        float A0 = fmaf(s_cf[0], sxi, fmaf(s_cf[3], X, s_cf[6]));
        float A1 = fmaf(s_cf[1], sxi, fmaf(s_cf[4], X, s_cf[7]));
        float A2 = fmaf(s_cf[2], sxi, fmaf(s_cf[5], X, s_cf[8]));
        float mA = fmaxf(A0, fmaxf(A1, A2));
        g_EA[myrow] = make_float4(__expf(A0 - mA), __expf(A1 - mA), __expf(A2 - mA), 0.f);
        float B0 = fmaf(s_cf[9],  sxi, fmaf(s_cf[12], X, s_cf[15]));
        float B1 = fmaf(s_cf[10], sxi, fmaf(s_cf[13], X, s_cf[16]));
        float B2 = fmaf(s_cf[11], sxi, fmaf(s_cf[14], X, s_cf[17]));
        float mB = fmaxf(B0, fmaxf(B1, B2));
        g_EB[myrow] = make_float4(__expf(B0 - mB), __expf(B1 - mB), __expf(B2 - mB), 0.f);
    }

    // ===== grid-wide ticket barrier (fences hoisted into one thread) ========
    __syncthreads();
    if (tid == 0) {
        __threadfence();                    // release (cumulative)
        unsigned long long ticket = atomicAdd(&g_bar, 1ULL);
        unsigned long long target = ticket - (ticket % GRID) + GRID;
        while (*(volatile unsigned long long*)&g_bar < target) { }
        __threadfence();                    // acquire
    }
    __syncthreads();

    // ============== Phase 2: TWO rows per warp, j-quarter split =============
    const int lane = tid & 31;
    const int warp = tid >> 5;              // 0..15
    const int p    = warp >> 2;             // row-pair 0..3
    const int q    = warp & 3;              // j-quarter
    const int i0   = bid * 8 + 2 * p;
    const int i1   = i0 + 1;
    const float4 eaA = g_EA[i0];
    const float4 eaB = g_EA[i1];

    // folded coefficients per row: q[m][k] = c2[k,m] * ea_k
    float qA0[3], qA1[3], qB0[3], qB1[3];
    #pragma unroll
    for (int k = 0; k < 3; k++) {
        float c20 = s_cc[(k * 2 + 0) * 3 + 2];
        float c21 = s_cc[(k * 2 + 1) * 3 + 2];
        qA0[k] = c20 * eaA.x * 0.f + c20 * ((const float*)&eaA)[k];  // placeholder fixed below
        qA0[k] = c20 * ((const float*)&eaA)[k];
        qA1[k] = c21 * ((const float*)&eaA)[k];
        qB0[k] = c20 * ((const float*)&eaB)[k];
        qB1[k] = c21 * ((const float*)&eaB)[k];
    }

    float tA0 = 0.f, tA1 = 0.f, tA2 = 0.f;
    float tB0 = 0.f, tB1 = 0.f, tB2 = 0.f;
    float2 aA0[4], aA1[4], aB0[4], aB1[4];
    #pragma unroll
    for (int bp = 0; bp < 4; bp++) {
        aA0[bp] = make_float2(0.f, 0.f); aA1[bp] = make_float2(0.f, 0.f);
        aB0[bp] = make_float2(0.f, 0.f); aB1[bp] = make_float2(0.f, 0.f);
    }

    #pragma unroll 1
    for (int u = 0; u < 2; u++) {
        const int jbase = q * 256 + u * 128 + lane;
        float4 eb[4];
        #pragma unroll
        for (int t = 0; t < 4; t++) eb[t] = g_EB[jbase + t * 32];

        float dA[4], dB[4];
        #pragma unroll
        for (int t = 0; t < 4; t++) {
            dA[t] = fmaf(eaA.x, eb[t].x, fmaf(eaA.y, eb[t].y, fmaf(eaA.z, eb[t].z, eb[t].w)));
            dB[t] = fmaf(eaB.x, eb[t].x, fmaf(eaB.y, eb[t].y, fmaf(eaB.z, eb[t].z, eb[t].w)));
        }
        // Montgomery-8 across both rows: d in (1,4] -> product <= 65536, safe
        float pr[8];
        pr[0] = dA[0];
        pr[1] = pr[0] * dA[1];
        pr[2] = pr[1] * dA[2];
        pr[3] = pr[2] * dA[3];
        pr[4] = pr[3] * dB[0];
        pr[5] = pr[4] * dB[1];
        pr[6] = pr[5] * dB[2];
        pr[7] = pr[6] * dB[3];
        float rr = __fdividef(1.f, pr[7]);
        float invA[4], invB[4];
        invB[3] = rr * pr[6];  rr *= dB[3];
        invB[2] = rr * pr[5];  rr *= dB[2];
        invB[1] = rr * pr[4];  rr *= dB[1];
        invB[0] = rr * pr[3];  rr *= dB[0];
        invA[3] = rr * pr[2];  rr *= dA[3];
        invA[2] = rr * pr[1];  rr *= dA[2];
        invA[1] = rr * pr[0];  rr *= dA[1];
        invA[0] = rr;

        #pragma unroll
        for (int t = 0; t < 4; t++) {
            const int j = jbase + t * 32;
            float4 xa = g_xt[2 * j];
            float4 xb = g_xt[2 * j + 1];
            float2 xp[4] = { make_float2(xa.x, xa.y), make_float2(xa.z, xa.w),
                             make_float2(xb.x, xb.y), make_float2(xb.z, xb.w) };
            // row A
            {
                float w0 = eb[t].x * invA[t];
                float w1 = eb[t].y * invA[t];
                float w2 = eb[t].z * invA[t];
                tA0 += w0; tA1 += w1; tA2 += w2;
                float s0 = fmaf(qA0[0], w0, fmaf(qA0[1], w1, qA0[2] * w2));
                float s1 = fmaf(qA1[0], w0, fmaf(qA1[1], w1, qA1[2] * w2));
                float2 sp0 = make_float2(s0, s0);
                float2 sp1 = make_float2(s1, s1);
                #pragma unroll
                for (int bp = 0; bp < 4; bp++) {
                    ffma2(aA0[bp], sp0, xp[bp]);
                    ffma2(aA1[bp], sp1, xp[bp]);
                }
            }
            // row B
            {
                float w0 = eb[t].x * invB[t];
                float w1 = eb[t].y * invB[t];
                float w2 = eb[t].z * invB[t];
                tB0 += w0; tB1 += w1; tB2 += w2;
                float s0 = fmaf(qB0[0], w0, fmaf(qB0[1], w1, qB0[2] * w2));
                float s1 = fmaf(qB1[0], w0, fmaf(qB1[1], w1, qB1[2] * w2));
                float2 sp0 = make_float2(s0, s0);
                float2 sp1 = make_float2(s1, s1);
                #pragma unroll
                for (int bp = 0; bp < 4; bp++) {
                    ffma2(aB0[bp], sp0, xp[bp]);
                    ffma2(aB1[bp], sp1, xp[bp]);
                }
            }
        }
    }

    // two 32-slot distributed exchange reductions (interleaved for ILP)
    float vA[32], vB[32];
    vA[0] = tA0; vA[1] = tA1; vA[2] = tA2;
    vB[0] = tB0; vB[1] = tB1; vB[2] = tB2;
    #pragma unroll
    for (int bp = 0; bp < 4; bp++) {
        vA[3 + 2 * bp]      = aA0[bp].x;  vA[3 + 2 * bp + 1]  = aA0[bp].y;
        vA[11 + 2 * bp]     = aA1[bp].x;  vA[11 + 2 * bp + 1] = aA1[bp].y;
        vB[3 + 2 * bp]      = aB0[bp].x;  vB[3 + 2 * bp + 1]  = aB0[bp].y;
        vB[11 + 2 * bp]     = aB1[bp].x;  vB[11 + 2 * bp + 1] = aB1[bp].y;
    }
    #pragma unroll
    for (int s = 19; s < 32; s++) { vA[s] = 0.f; vB[s] = 0.f; }

    #pragma unroll
    for (int lev = 0; lev < 5; lev++) {
        const int dd = 1 << lev;
        const int half = 16 >> lev;
        const bool up = (lane & dd) != 0;
        #pragma unroll
        for (int s = 0; s < half; s++) {
            float keepA = up ? vA[s + half] : vA[s];
            float sendA = up ? vA[s] : vA[s + half];
            float keepB = up ? vB[s + half] : vB[s];
            float sendB = up ? vB[s] : vB[s + half];
            vA[s] = keepA + __shfl_xor_sync(0xffffffffu, sendA, dd);
            vB[s] = keepB + __shfl_xor_sync(0xffffffffu, sendB, dd);
        }
    }
    const int br = ((lane & 1) << 4) | ((lane & 2) << 2) | (lane & 4)
                 | ((lane & 8) >> 2) | ((lane & 16) >> 4);
    s_v[warp][br]      = vA[0];
    s_v[warp][32 + br] = vB[0];
    __syncthreads();

    // q==0 warps: lanes 0..15 write both rows (lane>>3 = row, lane&7 = batch)
    if (q == 0 && lane < 16) {
        const int row  = lane >> 3;
        const int b    = lane & 7;
        const int i    = i0 + row;
        const int base = row * 32;
        const int w0i  = 4 * p;
        const float4 ea = row ? eaB : eaA;
        const float eav[3] = {ea.x, ea.y, ea.z};
        float xbi = ((const float*)&g_xt[2 * i])[b];
        float T0 = (s_v[w0i][base + 0] + s_v[w0i + 1][base + 0])
                 + (s_v[w0i + 2][base + 0] + s_v[w0i + 3][base + 0]);
        float T1 = (s_v[w0i][base + 1] + s_v[w0i + 1][base + 1])
                 + (s_v[w0i + 2][base + 1] + s_v[w0i + 3][base + 1]);
        float T2 = (s_v[w0i][base + 2] + s_v[w0i + 1][base + 2])
                 + (s_v[w0i + 2][base + 2] + s_v[w0i + 3][base + 2]);
        float V0 = (s_v[w0i][base + 3 + b] + s_v[w0i + 1][base + 3 + b])
                 + (s_v[w0i + 2][base + 3 + b] + s_v[w0i + 3][base + 3 + b]);
        float V1 = (s_v[w0i][base + 11 + b] + s_v[w0i + 1][base + 11 + b])
                 + (s_v[w0i + 2][base + 11 + b] + s_v[w0i + 3][base + 11 + b]);
        float eaT[3] = {eav[0] * T0, eav[1] * T1, eav[2] * T2};
        float ve0 = V0, ve1 = V1;
        #pragma unroll
        for (int k = 0; k < 3; k++) {
            ve0 += fmaf(xbi, s_cc[(k * 2 + 0) * 3 + 1], s_cc[(k * 2 + 0) * 3 + 0]) * eaT[k];
            ve1 += fmaf(xbi, s_cc[(k * 2 + 1) * 3 + 1], s_cc[(k * 2 + 1) * 3 + 0]) * eaT[k];
        }
        out[b * Nn + i] = xbi * (1.f + s_cc[20]) + s_cc[21]
                        + ve0 * s_cc[18] + ve1 * s_cc[19];
    }
}

extern "C" void kernel_launch(void* const* d_in, const int* in_sizes, int n_in,
                              void* d_out, int out_size)
{
    (void)in_sizes; (void)n_in; (void)out_size;
    k_all<<<GRID, NTHREAD>>>(
        (const float*)d_in[0],
        (const float*)d_in[1],  (const float*)d_in[2],
        (const float*)d_in[3],  (const float*)d_in[4],
        (const float*)d_in[5],  (const float*)d_in[6],
        (const float*)d_in[7],  (const float*)d_in[8],
        (const float*)d_in[9],  (const float*)d_in[10],
        (const float*)d_in[11], (const float*)d_in[12],
        (const float*)d_in[13], (const float*)d_in[14],
        (float*)d_out);
}